// round 10
// baseline (speedup 1.0000x reference)
#include <cuda_runtime.h>
#include <cuda_fp16.h>

// PolyConvFrame: Jacobi polynomial graph convolution.
#define N_NODE   100000
#define N_EDGE   1600000
#define D_FEAT   64
#define DEPTH    10
#define LSTRIDE  ((DEPTH + 1) * D_FEAT)   // 704 floats per node in output
#define SCAN_BS  1024
#define NBLK     ((N_NODE + SCAN_BS - 1) / SCAN_BS)   // 98
#define E_CAP    (N_EDGE + 3 * N_NODE)    // padded CSR capacity (rows padded to mult of 4)

// -------- device scratch (no allocation allowed) --------
__device__ int    g_deg[N_NODE];
__device__ int    g_rowptr[N_NODE + 1];
__device__ int    g_slot[N_NODE];
__device__ float  g_dinv[N_NODE];
__device__ __align__(16) int2 g_edge[E_CAP];   // {col, float_as_int(val)} interleaved
__device__ float  g_coef[(DEPTH + 1) * 4];
__device__ int    g_idx64;
__device__ int    g_blocksum[NBLK];
__device__ int    g_blockoff[NBLK];
__device__ __half g_xh[2 * N_NODE * D_FEAT];   // fp16 ping-pong mirror (gather source)
__device__ float  g_xf[2 * N_NODE * D_FEAT];   // fp32 ping-pong recurrence state

// grid barrier state
__device__ unsigned          g_bar_count;
__device__ volatile unsigned g_bar_sense;

// -------- 0. detect edge_index dtype (int64 vs int32), warp-parallel --------
__global__ void detect_kernel(const int* __restrict__ ei32) {
    int lane = threadIdx.x;
    const long long total32 = 2LL * N_EDGE * 2;
    int nonzero = 0;
    for (int k = lane; k < 256; k += 32) {
        long long pos = ((long long)k * (total32 / 256)) | 1;   // odd word = high half if int64
        if (pos < 2LL * N_EDGE && ei32[pos] != 0) nonzero = 1;  // stay in int32 bounds
    }
    unsigned any = __ballot_sync(0xFFFFFFFFu, nonzero);
    if (lane == 0) g_idx64 = (any == 0u) ? 1 : 0;
}

__device__ __forceinline__ int load_idx(const void* ei, long long pos, int is64) {
    return is64 ? (int)((const long long*)ei)[pos] : ((const int*)ei)[pos];
}

// -------- 1. zero counters --------
__global__ void zero_kernel() {
    int i = blockIdx.x * blockDim.x + threadIdx.x;
    if (i < N_NODE) { g_deg[i] = 0; g_slot[i] = 0; }
}

// -------- 2. out-degree histogram --------
__global__ void count_kernel(const void* __restrict__ ei) {
    int e = blockIdx.x * blockDim.x + threadIdx.x;
    if (e >= N_EDGE) return;
    int r = load_idx(ei, e, g_idx64);
    if ((unsigned)r < N_NODE) atomicAdd(&g_deg[r], 1);
}

// -------- 3a. per-block scan of PADDED degrees --------
__global__ void scan_a_kernel() {
    __shared__ int sh[SCAN_BS];
    int tid = threadIdx.x;
    int i = blockIdx.x * SCAN_BS + tid;
    int s = 0;
    if (i < N_NODE) { int d = g_deg[i]; s = (d + 3) & ~3; }
    sh[tid] = s;
    __syncthreads();
    for (int off = 1; off < SCAN_BS; off <<= 1) {
        int v = (tid >= off) ? sh[tid - off] : 0;
        __syncthreads();
        sh[tid] += v;
        __syncthreads();
    }
    if (i < N_NODE) g_rowptr[i] = sh[tid] - s;
    if (tid == SCAN_BS - 1) g_blocksum[blockIdx.x] = sh[tid];
}

// -------- 3b. scan the 98 block sums --------
__global__ void scan_b_kernel() {
    __shared__ int sh[128];
    int tid = threadIdx.x;
    int s = (tid < NBLK) ? g_blocksum[tid] : 0;
    sh[tid] = s;
    __syncthreads();
    for (int off = 1; off < 128; off <<= 1) {
        int v = (tid >= off) ? sh[tid - off] : 0;
        __syncthreads();
        sh[tid] += v;
        __syncthreads();
    }
    if (tid < NBLK) g_blockoff[tid] = sh[tid] - s;
    if (tid == 127) g_rowptr[N_NODE] = sh[127];
}

// -------- 3c. finalize rowptr, dinv, zero pad slots --------
__global__ void scan_c_kernel() {
    int i = blockIdx.x * blockDim.x + threadIdx.x;
    if (i >= N_NODE) return;
    int rp = g_rowptr[i] + g_blockoff[i >> 10];
    g_rowptr[i] = rp;
    int d = g_deg[i];
    g_dinv[i] = rsqrtf((float)(d == 0 ? 1 : d));
    int pd = (d + 3) & ~3;
    for (int j = d; j < pd; j++)
        g_edge[rp + j] = make_int2(0, 0);   // col 0, val +0.0f
}

// -------- 4. scatter edges into CSR (single 8B store per edge) --------
__global__ void scatter_kernel(const void* __restrict__ ei,
                               const float* __restrict__ edge_attr) {
    int e = blockIdx.x * blockDim.x + threadIdx.x;
    if (e >= N_EDGE) return;
    int is64 = g_idx64;
    int r = load_idx(ei, e, is64);
    int c = load_idx(ei, (long long)e + N_EDGE, is64);
    if ((unsigned)r >= N_NODE || (unsigned)c >= N_NODE) return;
    int pos = g_rowptr[r] + atomicAdd(&g_slot[r], 1);
    float v = g_dinv[r] * edge_attr[e] * g_dinv[c];
    g_edge[pos] = make_int2(c, __float_as_int(v));
}

// -------- 5. per-level recurrence coefficients --------
__global__ void coef_kernel(const float* __restrict__ alpha_params) {
    if (threadIdx.x != 0 || blockIdx.x != 0) return;
    const float BASEALPHA = 1.0f;
    const float a = 1.0f, b = 1.0f, l = -1.0f, r = 1.0f;
    float alphas[DEPTH + 1];
    for (int i = 0; i <= DEPTH; i++) alphas[i] = BASEALPHA * tanhf(alpha_params[i]);

    float coef1 = (a - b) * 0.5f - (a + b + 2.0f) * 0.5f * (l + r) / (r - l);
    float coef2 = (a + b + 2.0f) / (r - l);
    g_coef[1 * 4 + 0] = alphas[0] * coef2;
    g_coef[1 * 4 + 1] = alphas[0] * coef1;
    g_coef[1 * 4 + 2] = 0.0f;

    for (int L = 2; L <= DEPTH; L++) {
        float Lf = (float)L;
        float coef_l     = 2.0f * Lf * (Lf + a + b) * (2.0f * Lf - 2.0f + a + b);
        float coef_lm1_1 = (2.0f * Lf + a + b - 1.0f) * (2.0f * Lf + a + b) * (2.0f * Lf + a + b - 2.0f);
        float coef_lm1_2 = (2.0f * Lf + a + b - 1.0f) * (a * a - b * b);
        float coef_lm2   = 2.0f * (Lf - 1.0f + a) * (Lf - 1.0f + b) * (2.0f * Lf + a + b);
        float tmp1 = alphas[L - 1] * (coef_lm1_1 / coef_l);
        float tmp2 = alphas[L - 1] * (coef_lm1_2 / coef_l);
        float tmp3 = alphas[L - 1] * alphas[L - 2] * (coef_lm2 / coef_l);
        float tmp1_2 = tmp1 * (2.0f / (r - l));
        float tmp2_2 = tmp1 * ((r + l) / (r - l)) + tmp2;
        g_coef[L * 4 + 0] = tmp1_2;
        g_coef[L * 4 + 1] = -tmp2_2;
        g_coef[L * 4 + 2] = -tmp3;
    }
}

// -------- 6. level 0 init --------
__global__ void copy0_kernel(const float2* __restrict__ x, float* __restrict__ out) {
    int i = blockIdx.x * blockDim.x + threadIdx.x;
    const int NV = N_NODE * (D_FEAT / 2);
    if (i >= NV) return;
    int n = i >> 5;
    int d2 = i & 31;
    float2 v = x[i];
    *(float2*)(out + (size_t)n * LSTRIDE + d2 * 2) = v;
    *(float2*)(g_xf + (size_t)n * D_FEAT + d2 * 2) = v;
    *(__half2*)(g_xh + (size_t)n * D_FEAT + d2 * 2) = __float22half2_rn(v);
}

// gather 4 edges' fp16 rows and accumulate (p0 = edges e,e+1; p1 = e+2,e+3)
__device__ __forceinline__ void acc4(const __half* __restrict__ ysrc, int off,
                                     int4 p0, int4 p1, float& ax, float& ay) {
    float2 y0 = __half22float2(*(const __half2*)(ysrc + ((size_t)p0.x << 6) + off));
    float2 y1 = __half22float2(*(const __half2*)(ysrc + ((size_t)p0.z << 6) + off));
    float2 y2 = __half22float2(*(const __half2*)(ysrc + ((size_t)p1.x << 6) + off));
    float2 y3 = __half22float2(*(const __half2*)(ysrc + ((size_t)p1.z << 6) + off));
    float v0 = __int_as_float(p0.y), v1 = __int_as_float(p0.w);
    float v2 = __int_as_float(p1.y), v3 = __int_as_float(p1.w);
    ax += v0 * y0.x; ay += v0 * y0.y;
    ax += v1 * y1.x; ay += v1 * y1.y;
    ax += v2 * y2.x; ay += v2 * y2.y;
    ax += v3 * y3.x; ay += v3 * y3.y;
}

// finish one node: recurrence + stores (streaming store for out)
__device__ __forceinline__ void finish_node(
    int w, int L, int off, float ax, float ay,
    float cS, float c1, float c2,
    const float* __restrict__ x1b, float* __restrict__ x2b,
    __half* __restrict__ ydst, float* __restrict__ out)
{
    float2 x1 = *(const float2*)(x1b + ((size_t)w << 6) + off);
    float2 x2 = *(const float2*)(x2b + ((size_t)w << 6) + off); // junk*0 at L==1 (c2==0)
    float2 res;
    res.x = cS * ax + c1 * x1.x + c2 * x2.x;
    res.y = cS * ay + c1 * x1.y + c2 * x2.y;
    *(float2*)(x2b + ((size_t)w << 6) + off) = res;
    __stcs((float2*)(out + (size_t)w * LSTRIDE + L * D_FEAT + off), res);  // never read: bypass L2 retention
    if (L < DEPTH)
        *(__half2*)(ydst + ((size_t)w << 6) + off) = __float22half2_rn(res);
}

// -------- 7. fused ALL-LEVELS persistent kernel, TWO nodes in flight per warp --------
__global__ __launch_bounds__(256) void levels_kernel(float* __restrict__ out) {
    const int lane  = threadIdx.x & 31;
    const int wid   = threadIdx.x >> 5;
    const int wg    = blockIdx.x * 8 + wid;
    const int nwarp = gridDim.x * 8;
    const int off   = lane * 2;

    unsigned sense = g_bar_sense;

    for (int L = 1; L <= DEPTH; L++) {
        float cS = g_coef[L * 4 + 0];
        float c1 = g_coef[L * 4 + 1];
        float c2 = g_coef[L * 4 + 2];

        const __half* ysrc = g_xh + (size_t)((L - 1) & 1) * (N_NODE * D_FEAT);
        __half*       ydst = g_xh + (size_t)(L & 1)       * (N_NODE * D_FEAT);
        const float*  x1b  = g_xf + (size_t)((L - 1) & 1) * (N_NODE * D_FEAT);
        float*        x2b  = g_xf + (size_t)(L & 1)       * (N_NODE * D_FEAT);

        for (int w = wg; w < N_NODE; w += 2 * nwarp) {
            int wA = w;
            int wB = w + nwarp;
            bool hasB = (wB < N_NODE);

            int a  = g_rowptr[wA];
            int eA = g_rowptr[wA + 1];
            int b  = 0, eB = 0;
            if (hasB) { b = g_rowptr[wB]; eB = g_rowptr[wB + 1]; }

            float axA = 0.0f, ayA = 0.0f, axB = 0.0f, ayB = 0.0f;

            // common phase: both nodes' packets in flight (8 independent gathers)
            while (a < eA && b < eB) {
                int4 pA0 = *(const int4*)(g_edge + a);
                int4 pA1 = *(const int4*)(g_edge + a + 2);
                int4 pB0 = *(const int4*)(g_edge + b);
                int4 pB1 = *(const int4*)(g_edge + b + 2);
                acc4(ysrc, off, pA0, pA1, axA, ayA);
                acc4(ysrc, off, pB0, pB1, axB, ayB);
                a += 4; b += 4;
            }
            // tails
            for (; a < eA; a += 4) {
                int4 p0 = *(const int4*)(g_edge + a);
                int4 p1 = *(const int4*)(g_edge + a + 2);
                acc4(ysrc, off, p0, p1, axA, ayA);
            }
            for (; b < eB; b += 4) {
                int4 p0 = *(const int4*)(g_edge + b);
                int4 p1 = *(const int4*)(g_edge + b + 2);
                acc4(ysrc, off, p0, p1, axB, ayB);
            }

            finish_node(wA, L, off, axA, ayA, cS, c1, c2, x1b, x2b, ydst, out);
            if (hasB)
                finish_node(wB, L, off, axB, ayB, cS, c1, c2, x1b, x2b, ydst, out);
        }

        if (L < DEPTH) {   // grid barrier (backoff spin)
            __syncthreads();
            if (threadIdx.x == 0) {
                unsigned next = sense ^ 1;
                __threadfence();
                unsigned arrived = atomicAdd(&g_bar_count, 1);
                if (arrived == gridDim.x - 1) {
                    g_bar_count = 0;
                    __threadfence();
                    g_bar_sense = next;
                } else {
                    while (g_bar_sense != next) { __nanosleep(64); }
                }
                __threadfence();
            }
            __syncthreads();
            sense ^= 1;
        }
    }
}

extern "C" void kernel_launch(void* const* d_in, const int* in_sizes, int n_in,
                              void* d_out, int out_size) {
    const float* x            = (const float*)d_in[0];
    const float* edge_attr    = (const float*)d_in[1];
    const float* alpha_params = (const float*)d_in[2];
    const void*  edge_index   = d_in[3];
    float* out = (float*)d_out;

    (void)in_sizes; (void)n_in; (void)out_size;

    const int T = 256;
    detect_kernel <<<1, 32>>>((const int*)edge_index);
    zero_kernel   <<<(N_NODE + T - 1) / T, T>>>();
    count_kernel  <<<(N_EDGE + T - 1) / T, T>>>(edge_index);
    scan_a_kernel <<<NBLK, SCAN_BS>>>();
    scan_b_kernel <<<1, 128>>>();
    scan_c_kernel <<<(N_NODE + T - 1) / T, T>>>();
    scatter_kernel<<<(N_EDGE + T - 1) / T, T>>>(edge_index, edge_attr);
    coef_kernel   <<<1, 32>>>(alpha_params);

    const int NV2 = N_NODE * (D_FEAT / 2);
    copy0_kernel  <<<(NV2 + T - 1) / T, T>>>((const float2*)x, out);

    // Persistent grid: fully resident by construction (SMs x achievable occupancy).
    int nsm = 0, occ = 0;
    cudaDeviceGetAttribute(&nsm, cudaDevAttrMultiProcessorCount, 0);
    cudaOccupancyMaxActiveBlocksPerMultiprocessor(&occ, levels_kernel, 256, 0);
    if (nsm <= 0) nsm = 148;
    if (occ <= 0) occ = 1;
    int grid = nsm * occ;
    levels_kernel<<<grid, 256>>>(out);
}

// round 11
// speedup vs baseline: 1.5761x; 1.5761x over previous
#include <cuda_runtime.h>
#include <cuda_fp16.h>

// PolyConvFrame: Jacobi polynomial graph convolution.
#define N_NODE   100000
#define N_EDGE   1600000
#define D_FEAT   64
#define DEPTH    10
#define LSTRIDE  ((DEPTH + 1) * D_FEAT)   // 704 floats per node in output
#define SCAN_BS  1024
#define NBLK     ((N_NODE + SCAN_BS - 1) / SCAN_BS)   // 98
#define E_CAP    (N_EDGE + 3 * N_NODE)    // padded CSR capacity (rows padded to mult of 4)

// -------- device scratch (no allocation allowed) --------
__device__ int    g_deg[N_NODE];
__device__ int    g_rowptr[N_NODE + 1];
__device__ int    g_slot[N_NODE];
__device__ float  g_dinv[N_NODE];
__device__ __align__(16) int2 g_edge[E_CAP];   // {col, float_as_int(val)} interleaved
__device__ float  g_coef[(DEPTH + 1) * 4];
__device__ int    g_idx64;
__device__ int    g_blocksum[NBLK];
__device__ int    g_blockoff[NBLK];
__device__ __half g_xh[2 * N_NODE * D_FEAT];   // fp16 ping-pong: buf((L)&1) holds x_L after level L

// grid barrier state
__device__ unsigned          g_bar_count;
__device__ volatile unsigned g_bar_sense;

// -------- 0. detect edge_index dtype (int64 vs int32), warp-parallel --------
__global__ void detect_kernel(const int* __restrict__ ei32) {
    int lane = threadIdx.x;
    const long long total32 = 2LL * N_EDGE * 2;
    int nonzero = 0;
    for (int k = lane; k < 256; k += 32) {
        long long pos = ((long long)k * (total32 / 256)) | 1;   // odd word = high half if int64
        if (pos < 2LL * N_EDGE && ei32[pos] != 0) nonzero = 1;  // stay in int32 bounds
    }
    unsigned any = __ballot_sync(0xFFFFFFFFu, nonzero);
    if (lane == 0) g_idx64 = (any == 0u) ? 1 : 0;
}

__device__ __forceinline__ int load_idx(const void* ei, long long pos, int is64) {
    return is64 ? (int)((const long long*)ei)[pos] : ((const int*)ei)[pos];
}

// -------- 1. zero counters --------
__global__ void zero_kernel() {
    int i = blockIdx.x * blockDim.x + threadIdx.x;
    if (i < N_NODE) { g_deg[i] = 0; g_slot[i] = 0; }
}

// -------- 2. out-degree histogram --------
__global__ void count_kernel(const void* __restrict__ ei) {
    int e = blockIdx.x * blockDim.x + threadIdx.x;
    if (e >= N_EDGE) return;
    int r = load_idx(ei, e, g_idx64);
    if ((unsigned)r < N_NODE) atomicAdd(&g_deg[r], 1);
}

// -------- 3a. per-block scan of PADDED degrees --------
__global__ void scan_a_kernel() {
    __shared__ int sh[SCAN_BS];
    int tid = threadIdx.x;
    int i = blockIdx.x * SCAN_BS + tid;
    int s = 0;
    if (i < N_NODE) { int d = g_deg[i]; s = (d + 3) & ~3; }
    sh[tid] = s;
    __syncthreads();
    for (int off = 1; off < SCAN_BS; off <<= 1) {
        int v = (tid >= off) ? sh[tid - off] : 0;
        __syncthreads();
        sh[tid] += v;
        __syncthreads();
    }
    if (i < N_NODE) g_rowptr[i] = sh[tid] - s;
    if (tid == SCAN_BS - 1) g_blocksum[blockIdx.x] = sh[tid];
}

// -------- 3b. scan the 98 block sums --------
__global__ void scan_b_kernel() {
    __shared__ int sh[128];
    int tid = threadIdx.x;
    int s = (tid < NBLK) ? g_blocksum[tid] : 0;
    sh[tid] = s;
    __syncthreads();
    for (int off = 1; off < 128; off <<= 1) {
        int v = (tid >= off) ? sh[tid - off] : 0;
        __syncthreads();
        sh[tid] += v;
        __syncthreads();
    }
    if (tid < NBLK) g_blockoff[tid] = sh[tid] - s;
    if (tid == 127) g_rowptr[N_NODE] = sh[127];
}

// -------- 3c. finalize rowptr, dinv, zero pad slots --------
__global__ void scan_c_kernel() {
    int i = blockIdx.x * blockDim.x + threadIdx.x;
    if (i >= N_NODE) return;
    int rp = g_rowptr[i] + g_blockoff[i >> 10];
    g_rowptr[i] = rp;
    int d = g_deg[i];
    g_dinv[i] = rsqrtf((float)(d == 0 ? 1 : d));
    int pd = (d + 3) & ~3;
    for (int j = d; j < pd; j++)
        g_edge[rp + j] = make_int2(0, 0);   // col 0, val +0.0f
}

// -------- 4. scatter edges into CSR (single 8B store per edge) --------
__global__ void scatter_kernel(const void* __restrict__ ei,
                               const float* __restrict__ edge_attr) {
    int e = blockIdx.x * blockDim.x + threadIdx.x;
    if (e >= N_EDGE) return;
    int is64 = g_idx64;
    int r = load_idx(ei, e, is64);
    int c = load_idx(ei, (long long)e + N_EDGE, is64);
    if ((unsigned)r >= N_NODE || (unsigned)c >= N_NODE) return;
    int pos = g_rowptr[r] + atomicAdd(&g_slot[r], 1);
    float v = g_dinv[r] * edge_attr[e] * g_dinv[c];
    g_edge[pos] = make_int2(c, __float_as_int(v));
}

// -------- 5. per-level recurrence coefficients --------
__global__ void coef_kernel(const float* __restrict__ alpha_params) {
    if (threadIdx.x != 0 || blockIdx.x != 0) return;
    const float BASEALPHA = 1.0f;
    const float a = 1.0f, b = 1.0f, l = -1.0f, r = 1.0f;
    float alphas[DEPTH + 1];
    for (int i = 0; i <= DEPTH; i++) alphas[i] = BASEALPHA * tanhf(alpha_params[i]);

    float coef1 = (a - b) * 0.5f - (a + b + 2.0f) * 0.5f * (l + r) / (r - l);
    float coef2 = (a + b + 2.0f) / (r - l);
    g_coef[1 * 4 + 0] = alphas[0] * coef2;
    g_coef[1 * 4 + 1] = alphas[0] * coef1;
    g_coef[1 * 4 + 2] = 0.0f;

    for (int L = 2; L <= DEPTH; L++) {
        float Lf = (float)L;
        float coef_l     = 2.0f * Lf * (Lf + a + b) * (2.0f * Lf - 2.0f + a + b);
        float coef_lm1_1 = (2.0f * Lf + a + b - 1.0f) * (2.0f * Lf + a + b) * (2.0f * Lf + a + b - 2.0f);
        float coef_lm1_2 = (2.0f * Lf + a + b - 1.0f) * (a * a - b * b);
        float coef_lm2   = 2.0f * (Lf - 1.0f + a) * (Lf - 1.0f + b) * (2.0f * Lf + a + b);
        float tmp1 = alphas[L - 1] * (coef_lm1_1 / coef_l);
        float tmp2 = alphas[L - 1] * (coef_lm1_2 / coef_l);
        float tmp3 = alphas[L - 1] * alphas[L - 2] * (coef_lm2 / coef_l);
        float tmp1_2 = tmp1 * (2.0f / (r - l));
        float tmp2_2 = tmp1 * ((r + l) / (r - l)) + tmp2;
        g_coef[L * 4 + 0] = tmp1_2;
        g_coef[L * 4 + 1] = -tmp2_2;
        g_coef[L * 4 + 2] = -tmp3;
    }
}

// -------- 6. level 0 init: out slice 0 (fp32) + fp16 mirror buf 0 --------
__global__ void copy0_kernel(const float2* __restrict__ x, float* __restrict__ out) {
    int i = blockIdx.x * blockDim.x + threadIdx.x;
    const int NV = N_NODE * (D_FEAT / 2);
    if (i >= NV) return;
    int n = i >> 5;
    int d2 = i & 31;
    float2 v = x[i];
    __stcs((float2*)(out + (size_t)n * LSTRIDE + d2 * 2), v);
    *(__half2*)(g_xh + (size_t)n * D_FEAT + d2 * 2) = __float22half2_rn(v);
}

// gather 4 edges' fp16 rows and accumulate (p0 = edges e,e+1; p1 = e+2,e+3)
__device__ __forceinline__ void acc4(const __half* __restrict__ ysrc, int off,
                                     int4 p0, int4 p1, float& ax, float& ay) {
    float2 y0 = __half22float2(*(const __half2*)(ysrc + ((size_t)p0.x << 6) + off));
    float2 y1 = __half22float2(*(const __half2*)(ysrc + ((size_t)p0.z << 6) + off));
    float2 y2 = __half22float2(*(const __half2*)(ysrc + ((size_t)p1.x << 6) + off));
    float2 y3 = __half22float2(*(const __half2*)(ysrc + ((size_t)p1.z << 6) + off));
    float v0 = __int_as_float(p0.y), v1 = __int_as_float(p0.w);
    float v2 = __int_as_float(p1.y), v3 = __int_as_float(p1.w);
    ax += v0 * y0.x; ay += v0 * y0.y;
    ax += v1 * y1.x; ay += v1 * y1.y;
    ax += v2 * y2.x; ay += v2 * y2.y;
    ax += v3 * y3.x; ay += v3 * y3.y;
}

// -------- 7. fused ALL-LEVELS persistent kernel, fp16-only recurrence state --------
__global__ __launch_bounds__(256) void levels_kernel(float* __restrict__ out) {
    const int lane  = threadIdx.x & 31;
    const int wid   = threadIdx.x >> 5;
    const int wg    = blockIdx.x * 8 + wid;
    const int nwarp = gridDim.x * 8;
    const int off   = lane * 2;

    unsigned sense = g_bar_sense;

    for (int L = 1; L <= DEPTH; L++) {
        float cS = g_coef[L * 4 + 0];
        float c1 = g_coef[L * 4 + 1];
        float c2 = g_coef[L * 4 + 2];

        const __half* ysrc = g_xh + (size_t)((L - 1) & 1) * (N_NODE * D_FEAT); // x_{L-1}
        __half*       ydst = g_xh + (size_t)(L & 1)       * (N_NODE * D_FEAT); // holds x_{L-2}; becomes x_L

        for (int w = wg; w < N_NODE; w += nwarp) {
            int start = g_rowptr[w];        // multiple of 4
            int end   = g_rowptr[w + 1];

            float ax = 0.0f, ay = 0.0f;
            if (end > start) {
                int4 p0 = *(const int4*)(g_edge + start);       // prefetch first packet
                int4 p1 = *(const int4*)(g_edge + start + 2);
                int e = start + 4;
                for (; e < end; e += 4) {
                    int4 n0 = *(const int4*)(g_edge + e);       // next packet overlaps gathers
                    int4 n1 = *(const int4*)(g_edge + e + 2);
                    acc4(ysrc, off, p0, p1, ax, ay);
                    p0 = n0; p1 = n1;
                }
                acc4(ysrc, off, p0, p1, ax, ay);                // final packet
            }

            // recurrence operands from fp16 mirrors (x2 read before overwrite, same warp)
            float2 x1 = __half22float2(*(const __half2*)(ysrc + ((size_t)w << 6) + off));
            float2 x2 = __half22float2(*(const __half2*)(ydst + ((size_t)w << 6) + off)); // *0 at L==1
            float2 res;
            res.x = cS * ax + c1 * x1.x + c2 * x2.x;
            res.y = cS * ay + c1 * x1.y + c2 * x2.y;
            __stcs((float2*)(out + (size_t)w * LSTRIDE + L * D_FEAT + off), res); // never re-read
            *(__half2*)(ydst + ((size_t)w << 6) + off) = __float22half2_rn(res);  // x_L state
        }

        if (L < DEPTH) {   // grid barrier (backoff spin)
            __syncthreads();
            if (threadIdx.x == 0) {
                unsigned next = sense ^ 1;
                __threadfence();
                unsigned arrived = atomicAdd(&g_bar_count, 1);
                if (arrived == gridDim.x - 1) {
                    g_bar_count = 0;
                    __threadfence();
                    g_bar_sense = next;
                } else {
                    while (g_bar_sense != next) { __nanosleep(64); }
                }
                __threadfence();
            }
            __syncthreads();
            sense ^= 1;
        }
    }
}

extern "C" void kernel_launch(void* const* d_in, const int* in_sizes, int n_in,
                              void* d_out, int out_size) {
    const float* x            = (const float*)d_in[0];
    const float* edge_attr    = (const float*)d_in[1];
    const float* alpha_params = (const float*)d_in[2];
    const void*  edge_index   = d_in[3];
    float* out = (float*)d_out;

    (void)in_sizes; (void)n_in; (void)out_size;

    const int T = 256;
    detect_kernel <<<1, 32>>>((const int*)edge_index);
    zero_kernel   <<<(N_NODE + T - 1) / T, T>>>();
    count_kernel  <<<(N_EDGE + T - 1) / T, T>>>(edge_index);
    scan_a_kernel <<<NBLK, SCAN_BS>>>();
    scan_b_kernel <<<1, 128>>>();
    scan_c_kernel <<<(N_NODE + T - 1) / T, T>>>();
    scatter_kernel<<<(N_EDGE + T - 1) / T, T>>>(edge_index, edge_attr);
    coef_kernel   <<<1, 32>>>(alpha_params);

    const int NV2 = N_NODE * (D_FEAT / 2);
    copy0_kernel  <<<(NV2 + T - 1) / T, T>>>((const float2*)x, out);

    // Persistent grid: fully resident by construction (SMs x achievable occupancy).
    int nsm = 0, occ = 0;
    cudaDeviceGetAttribute(&nsm, cudaDevAttrMultiProcessorCount, 0);
    cudaOccupancyMaxActiveBlocksPerMultiprocessor(&occ, levels_kernel, 256, 0);
    if (nsm <= 0) nsm = 148;
    if (occ <= 0) occ = 1;
    int grid = nsm * occ;
    levels_kernel<<<grid, 256>>>(out);
}